// round 2
// baseline (speedup 1.0000x reference)
#include <cuda_runtime.h>
#include <cstdint>

#define EMB   1024
#define HID   128
#define PW    64
#define KTOT  1088   // sim (1024) + pw (64) rows of W1, i.e. W1 rows [2048, 3136)
#define NAP   56     // ants padded: 8 warps * 7 ants

// Scratch (allocation-free rule: __device__ globals)
__device__ float g_Aproj[512 * HID];
__device__ float g_Bproj[10016 * HID];
__device__ int   g_idx64;   // 1 if top_indices buffer is int64, else 0

// ---------- packed f32x2 helpers (Blackwell) ----------
__device__ __forceinline__ unsigned long long pk2(float lo, float hi) {
    unsigned long long r;
    asm("mov.b64 %0, {%1, %2};" : "=l"(r) : "f"(lo), "f"(hi));
    return r;
}
__device__ __forceinline__ void upk2(unsigned long long v, float& lo, float& hi) {
    asm("mov.b64 {%0, %1}, %2;" : "=f"(lo), "=f"(hi) : "l"(v));
}
__device__ __forceinline__ void fma2(unsigned long long& d, unsigned long long a, unsigned long long b) {
    asm("fma.rn.f32x2 %0, %1, %2, %0;" : "+l"(d) : "l"(a), "l"(b));
}
__device__ __forceinline__ unsigned long long mul2(unsigned long long a, unsigned long long b) {
    unsigned long long r;
    asm("mul.rn.f32x2 %0, %1, %2;" : "=l"(r) : "l"(a), "l"(b));
    return r;
}

// ---------- idx dtype detection ----------
// If the index buffer is int64 (little-endian, values in [0, 10000)), every
// odd 32-bit word is 0. For genuine int32 random indices that is impossible
// over 128 samples. Single thread, deterministic.
__global__ void detect_idx_kernel(const unsigned* __restrict__ w, int n_words) {
    unsigned acc = 0;
    int m = n_words < 256 ? n_words : 256;
    for (int i = 1; i < m; i += 2) acc |= w[i];
    g_idx64 = (acc == 0u) ? 1 : 0;
}

__device__ __forceinline__ int load_idx(const void* p, size_t pos, int is64) {
    return is64 ? (int)((const long long*)p)[pos] : ((const int*)p)[pos];
}

// ---------- projection kernel: out[m,k] = X[m,:] @ W (+ bias) ----------
// X: [n_rows, 1024], W: [1024, 128] row-major slice. 32 rows per block,
// 8 warps x 4 rows each; each lane owns 4 output columns.
template<int HAS_BIAS>
__global__ __launch_bounds__(256)
void proj_kernel(const float* __restrict__ X, int n_rows,
                 const float* __restrict__ W,
                 const float* __restrict__ bias,
                 int which_out) {
    __shared__ float xs[32 * 128];   // 16 KB e-chunk tile
    const int tid  = threadIdx.x;
    const int lane = tid & 31;
    const int wid  = tid >> 5;
    const int row0 = blockIdx.x * 32;
    float* __restrict__ out = which_out ? g_Bproj : g_Aproj;

    unsigned long long acc01[4], acc23[4];
#pragma unroll
    for (int r = 0; r < 4; r++) { acc01[r] = 0ull; acc23[r] = 0ull; }

    for (int ec = 0; ec < EMB; ec += 128) {
        // stage 32 rows x 128 e-cols
#pragma unroll
        for (int it = 0; it < 4; it++) {
            int id = tid + it * 256;          // 1024 float4 slots
            int r  = id >> 5;
            int e4 = id & 31;
            int m  = min(row0 + r, n_rows - 1);
            float4 v = *(const float4*)(X + (size_t)m * EMB + ec + e4 * 4);
            *(float4*)(xs + r * 128 + e4 * 4) = v;
        }
        __syncthreads();
        const float* wp = W + (size_t)ec * HID + lane * 4;
#pragma unroll 4
        for (int e = 0; e < 128; e++) {
            float4 w = *(const float4*)(wp + (size_t)e * HID);
            unsigned long long w01 = pk2(w.x, w.y);
            unsigned long long w23 = pk2(w.z, w.w);
#pragma unroll
            for (int r = 0; r < 4; r++) {
                float xv = xs[(wid * 4 + r) * 128 + e];
                unsigned long long x2 = pk2(xv, xv);
                fma2(acc01[r], x2, w01);
                fma2(acc23[r], x2, w23);
            }
        }
        __syncthreads();
    }

    float bb0 = 0.f, bb1 = 0.f, bb2 = 0.f, bb3 = 0.f;
    if (HAS_BIAS) {
        bb0 = bias[lane * 4 + 0]; bb1 = bias[lane * 4 + 1];
        bb2 = bias[lane * 4 + 2]; bb3 = bias[lane * 4 + 3];
    }
#pragma unroll
    for (int r = 0; r < 4; r++) {
        int m = row0 + wid * 4 + r;
        if (m < n_rows) {
            float4 o;
            upk2(acc01[r], o.x, o.y);
            upk2(acc23[r], o.z, o.w);
            o.x += bb0; o.y += bb1; o.z += bb2; o.w += bb3;
            *(float4*)(out + (size_t)m * HID + lane * 4) = o;
        }
    }
}

// ---------- fused per-pair kernel ----------
// One block per batch row b. 8 warps; warp w owns ants [7w, 7w+7) (padded to 56).
// Each lane owns 4 of the 128 hidden columns.
// h[a,k] = Aproj[b,k] + Bproj[idx[a],k]
//        + sum_e am[b,e]*bm[idx[a],e]*W1[2048+e,k]   (sim)
//        + sum_p pw[b,a,p]*W1[3072+p,k]              (pw)
// then LeakyReLU, dot with W_out, + b_out + rough; dummy EPS column prepended.
__global__ __launch_bounds__(256, 2)
void pair_scorer_kernel(const float* __restrict__ all_mentions,
                        const float* __restrict__ mentions_batch,
                        const float* __restrict__ pw_batch,
                        const void*  __restrict__ top_idx,
                        const float* __restrict__ rough,
                        const float* __restrict__ W1,
                        const float* __restrict__ W_out,
                        const float* __restrict__ b_out,
                        float* __restrict__ out,
                        int n_ants) {
    __shared__ float am_s[KTOT];          // am extended with 1.0f for pw rows
    __shared__ float val_s[NAP * 128];    // 56 x 128 operand tile (28 KB)
    __shared__ int   idx_s[NAP];

    const int b    = blockIdx.x;
    const int tid  = threadIdx.x;
    const int lane = tid & 31;
    const int wid  = tid >> 5;

    if (tid < NAP) {
        int is64 = g_idx64;
        size_t pos = (size_t)b * n_ants + min(tid, n_ants - 1);
        idx_s[tid] = load_idx(top_idx, pos, is64);
    }
    for (int i = tid; i < KTOT; i += 256)
        am_s[i] = (i < EMB) ? mentions_batch[(size_t)b * EMB + i] : 1.0f;
    __syncthreads();

    // init accumulators with Aproj + Bproj
    unsigned long long acc01[7], acc23[7];
    {
        float4 ap = *(const float4*)(g_Aproj + (size_t)b * HID + lane * 4);
#pragma unroll
        for (int j = 0; j < 7; j++) {
            int a   = wid * 7 + j;
            int row = idx_s[a];
            float4 bp = *(const float4*)(g_Bproj + (size_t)row * HID + lane * 4);
            acc01[j] = pk2(ap.x + bp.x, ap.y + bp.y);
            acc23[j] = pk2(ap.z + bp.z, ap.w + bp.w);
        }
    }

    for (int vc = 0; vc < KTOT; vc += 128) {
        const int L = min(128, KTOT - vc);   // 128 (sim) or 64 (pw tail)
        if (vc < EMB) {
            // gather bm chunk: val[a][e] = all_mentions[idx[a]][vc+e]
#pragma unroll
            for (int it = 0; it < 7; it++) {
                int id = tid + it * 256;     // 56*32 = 1792 float4 slots
                int a  = id >> 5;
                int e4 = id & 31;
                int row = idx_s[a];
                float4 v = *(const float4*)(all_mentions + (size_t)row * EMB + vc + e4 * 4);
                *(float4*)(val_s + a * 128 + e4 * 4) = v;
            }
        } else {
            // pw chunk: val[a][p] = pw[b,a,p]
            for (int id = tid; id < NAP * 16; id += 256) {
                int a  = id >> 4;
                int p4 = id & 15;
                int al = min(a, n_ants - 1);
                float4 v = *(const float4*)(pw_batch + ((size_t)b * n_ants + al) * PW + p4 * 4);
                *(float4*)(val_s + a * 128 + p4 * 4) = v;
            }
        }
        __syncthreads();

        const float* wp  = W1 + (size_t)(2 * EMB + vc) * HID + lane * 4;
        const float* amp = am_s + vc;
        const float* vlp = val_s + wid * 7 * 128;
#pragma unroll 2
        for (int e = 0; e < L; e++) {
            float4 w = *(const float4*)(wp + (size_t)e * HID);
            float  s = amp[e];
            unsigned long long s2   = pk2(s, s);
            unsigned long long wa01 = mul2(pk2(w.x, w.y), s2);
            unsigned long long wa23 = mul2(pk2(w.z, w.w), s2);
#pragma unroll
            for (int j = 0; j < 7; j++) {
                float bv = vlp[j * 128 + e];
                unsigned long long b2 = pk2(bv, bv);
                fma2(acc01[j], b2, wa01);
                fma2(acc23[j], b2, wa23);
            }
        }
        __syncthreads();
    }

    // epilogue: LeakyReLU -> dot W_out -> warp reduce -> store
    float4 wo = *(const float4*)(W_out + lane * 4);
    float  bo = b_out[0];
#pragma unroll
    for (int j = 0; j < 7; j++) {
        float h0, h1, h2, h3;
        upk2(acc01[j], h0, h1);
        upk2(acc23[j], h2, h3);
        h0 = fmaxf(h0, 0.f) + 0.01f * fminf(h0, 0.f);
        h1 = fmaxf(h1, 0.f) + 0.01f * fminf(h1, 0.f);
        h2 = fmaxf(h2, 0.f) + 0.01f * fminf(h2, 0.f);
        h3 = fmaxf(h3, 0.f) + 0.01f * fminf(h3, 0.f);
        float p = h0 * wo.x + h1 * wo.y + h2 * wo.z + h3 * wo.w;
#pragma unroll
        for (int off = 16; off; off >>= 1)
            p += __shfl_xor_sync(0xffffffffu, p, off);
        int a = wid * 7 + j;
        if (lane == 0 && a < n_ants)
            out[(size_t)b * (n_ants + 1) + 1 + a] =
                rough[(size_t)b * n_ants + a] + bo + p;
    }
    if (tid == 0) out[(size_t)b * (n_ants + 1)] = 1e-7f;
}

extern "C" void kernel_launch(void* const* d_in, const int* in_sizes, int n_in,
                              void* d_out, int out_size) {
    const float* all_m = (const float*)d_in[0];
    const float* m_b   = (const float*)d_in[1];
    const float* pw    = (const float*)d_in[2];
    const void*  idx   = d_in[3];
    const float* rough = (const float*)d_in[4];
    const float* W1    = (const float*)d_in[5];
    const float* b1    = (const float*)d_in[6];
    const float* Wo    = (const float*)d_in[7];
    const float* bo    = (const float*)d_in[8];
    float* out = (float*)d_out;

    const int n_mentions = in_sizes[0] / EMB;   // 10000
    const int batch      = in_sizes[1] / EMB;   // 512
    const int n_ants     = in_sizes[3] / batch; // 50

    // detect int32 vs int64 index buffer (sets g_idx64)
    detect_idx_kernel<<<1, 1>>>((const unsigned*)idx, in_sizes[3]);
    // A_proj = mentions_batch @ W1[0:1024] + b1
    proj_kernel<1><<<(batch + 31) / 32, 256>>>(m_b, batch, W1, b1, 0);
    // B_proj = all_mentions @ W1[1024:2048]
    proj_kernel<0><<<(n_mentions + 31) / 32, 256>>>(all_m, n_mentions,
                                                    W1 + (size_t)EMB * HID, nullptr, 1);
    // fused sim+pw GEMM + FFNN epilogue
    pair_scorer_kernel<<<batch, 256>>>(all_m, m_b, pw, idx, rough, W1, Wo, bo,
                                       out, n_ants);
}

// round 5
// speedup vs baseline: 2.0448x; 2.0448x over previous
#include <cuda_runtime.h>
#include <cstdint>

#define EMB    1024
#define HID    128
#define PW     64
#define KSEG   2112          // W1 rows [1024,3136): bm(1024) + sim(1024) + pw(64)
#define NCHUNK 34            // 32 e-chunks (bm+sim paired, K_eff=64) + 2 pw chunks (K=32)
#define APAD   36            // row pad (floats) for conflict-free tf32 fragment LDS
#define EPSV   1e-7f

// -------------------- device scratch (no allocs allowed) --------------------
__device__ float g_Aproj[512 * HID];
__device__ float g_W1T[HID * KSEG];   // W1T[n][k] = tf32_rna(W1[1024+k][n])
__device__ int   g_idx64;

// -------------------- small helpers --------------------
__device__ __forceinline__ uint32_t smem_u32(const void* p) {
    uint32_t a;
    asm("{ .reg .u64 t; cvta.to.shared.u64 t, %1; cvt.u32.u64 %0, t; }" : "=r"(a) : "l"(p));
    return a;
}
__device__ __forceinline__ unsigned long long to_global(const void* p) {
    unsigned long long g;
    asm("cvta.to.global.u64 %0, %1;" : "=l"(g) : "l"(p));
    return g;
}
#define CP16(dst_s32, src_g64) \
    asm volatile("cp.async.cg.shared.global [%0], [%1], 16;" :: "r"(dst_s32), "l"(src_g64) : "memory")
#define CP_COMMIT() asm volatile("cp.async.commit_group;" ::: "memory")
#define CP_WAIT1()  asm volatile("cp.async.wait_group 1;" ::: "memory")
#define CP_WAIT0()  asm volatile("cp.async.wait_group 0;" ::: "memory")

__device__ __forceinline__ void mma_tf32(float c[4], uint32_t a0, uint32_t a1, uint32_t a2, uint32_t a3,
                                         uint32_t b0, uint32_t b1) {
    asm volatile("mma.sync.aligned.m16n8k8.row.col.f32.tf32.tf32.f32 "
                 "{%0,%1,%2,%3}, {%4,%5,%6,%7}, {%8,%9}, {%0,%1,%2,%3};"
                 : "+f"(c[0]), "+f"(c[1]), "+f"(c[2]), "+f"(c[3])
                 : "r"(a0), "r"(a1), "r"(a2), "r"(a3), "r"(b0), "r"(b1));
}

// -------------------- idx dtype detection --------------------
__global__ void detect_idx_kernel(const unsigned* __restrict__ w, int n_words) {
    unsigned acc = 0;
    int m = n_words < 256 ? n_words : 256;
    for (int i = 1; i < m; i += 2) acc |= w[i];
    g_idx64 = (acc == 0u) ? 1 : 0;
}
__device__ __forceinline__ int load_idx(const void* p, size_t pos, int is64) {
    return is64 ? (int)((const long long*)p)[pos] : ((const int*)p)[pos];
}

// -------------------- W1 transpose + tf32 round: g_W1T[n][k] = rna(W1[1024+k][n]) --------------------
__global__ __launch_bounds__(256)
void transpose_w1_kernel(const float* __restrict__ W1) {
    __shared__ float s[32][33];
    const int kb = blockIdx.x * 32, nb = blockIdx.y * 32;
    const int tx = threadIdx.x & 31, ty = threadIdx.x >> 5;
#pragma unroll
    for (int j = 0; j < 4; j++) {
        int k = ty + 8 * j;
        s[k][tx] = W1[(size_t)(1024 + kb + k) * HID + nb + tx];
    }
    __syncthreads();
#pragma unroll
    for (int j = 0; j < 4; j++) {
        int y = ty + 8 * j;
        float v = s[tx][y];
        uint32_t tv;
        asm("cvt.rna.tf32.f32 %0, %1;" : "=r"(tv) : "f"(v));
        g_W1T[(size_t)(nb + y) * KSEG + kb + tx] = __uint_as_float(tv);
    }
}

// -------------------- Aproj (fp32 SIMT, exact): g_Aproj = mentions_batch @ W1[0:1024] + b1 ----------
__device__ __forceinline__ unsigned long long pk2(float lo, float hi) {
    unsigned long long r;
    asm("mov.b64 %0, {%1, %2};" : "=l"(r) : "f"(lo), "f"(hi));
    return r;
}
__device__ __forceinline__ void upk2(unsigned long long v, float& lo, float& hi) {
    asm("mov.b64 {%0, %1}, %2;" : "=f"(lo), "=f"(hi) : "l"(v));
}
__device__ __forceinline__ void fma2(unsigned long long& d, unsigned long long a, unsigned long long b) {
    asm("fma.rn.f32x2 %0, %1, %2, %0;" : "+l"(d) : "l"(a), "l"(b));
}
__global__ __launch_bounds__(256)
void aproj_kernel(const float* __restrict__ X, int n_rows,
                  const float* __restrict__ W, const float* __restrict__ bias) {
    __shared__ float xs[32 * 128];
    const int tid = threadIdx.x, lane = tid & 31, wid = tid >> 5;
    const int row0 = blockIdx.x * 32;
    unsigned long long acc01[4] = {0,0,0,0}, acc23[4] = {0,0,0,0};
    for (int ec = 0; ec < EMB; ec += 128) {
#pragma unroll
        for (int it = 0; it < 4; it++) {
            int id = tid + it * 256, r = id >> 5, e4 = id & 31;
            int m = min(row0 + r, n_rows - 1);
            *(float4*)(xs + r * 128 + e4 * 4) =
                *(const float4*)(X + (size_t)m * EMB + ec + e4 * 4);
        }
        __syncthreads();
        const float* wp = W + (size_t)ec * HID + lane * 4;
#pragma unroll 4
        for (int e = 0; e < 128; e++) {
            float4 w = *(const float4*)(wp + (size_t)e * HID);
            unsigned long long w01 = pk2(w.x, w.y), w23 = pk2(w.z, w.w);
#pragma unroll
            for (int r = 0; r < 4; r++) {
                float xv = xs[(wid * 4 + r) * 128 + e];
                unsigned long long x2 = pk2(xv, xv);
                fma2(acc01[r], x2, w01);
                fma2(acc23[r], x2, w23);
            }
        }
        __syncthreads();
    }
    float4 bb = *(const float4*)(bias + lane * 4);
#pragma unroll
    for (int r = 0; r < 4; r++) {
        int m = row0 + wid * 4 + r;
        if (m < n_rows) {
            float4 o;
            upk2(acc01[r], o.x, o.y);
            upk2(acc23[r], o.z, o.w);
            o.x += bb.x; o.y += bb.y; o.z += bb.z; o.w += bb.w;
            *(float4*)(g_Aproj + (size_t)m * HID + lane * 4) = o;
        }
    }
}

// -------------------- fused mma.sync pair kernel --------------------
// Block: 4 batch rows -> M=256 (4 x 64 ants padded), N=128 hidden. grid = batch/4 = 128.
// 8 warps; warp w owns M rows [32w, 32w+32), all 128 N cols. bq = w>>1.
// smem byte map (dynamic):
#define OFF_IDX    0                     // 256 ints
#define OFF_WOUT   1024                  // 128 f
#define OFF_APROJ  1536                  // 512 f
#define OFF_AM     4096                  // 4 x 1024 f (am rows for this block)
#define OFF_STAGE  20480                 // 2 stages x (A[256][36] + Bh[128][36] + Bs[128][36])
#define STAGE_B    (256*APAD*4 + 2*128*APAD*4)   // 73728
#define OFF_BH     (256*APAD*4)          // within stage
#define OFF_BS     (256*APAD*4 + 128*APAD*4)
#define SMEM_TOTAL (OFF_STAGE + 2*STAGE_B)       // 167936

struct StageCtx {
    unsigned long long all_m_g, w1t_g, pw_g;
    int b0, n_ants;
};

__device__ __forceinline__ void stage_chunk(int c, char* smem, uint32_t sbase,
                                            const int* idx_s, const StageCtx& cx, int tid) {
    const uint32_t stg = sbase + OFF_STAGE + (uint32_t)(c & 1) * STAGE_B;
    if (c < 32) {
        const int ec = c * 32;
        // A: gather bm rows, 256 rows x 8 float4
#pragma unroll
        for (int it = 0; it < 8; it++) {
            int id = tid + it * 256;
            int r = id >> 3, f4 = id & 7;
            unsigned long long src = cx.all_m_g +
                ((size_t)idx_s[r] * EMB + ec + f4 * 4) * 4ull;
            CP16(stg + (uint32_t)(r * (APAD * 4) + f4 * 16), src);
        }
        // B: Bh = W1T[:, ec..ec+32), Bs = W1T[:, 1024+ec..)
#pragma unroll
        for (int it = 0; it < 8; it++) {
            int id = tid + it * 256;
            int seg = id >> 10, n = (id >> 3) & 127, f4 = id & 7;
            unsigned long long src = cx.w1t_g +
                ((size_t)n * KSEG + (seg ? 1024 + ec : ec) + f4 * 4) * 4ull;
            uint32_t dst = stg + (seg ? OFF_BS : OFF_BH) + (uint32_t)(n * (APAD * 4) + f4 * 16);
            CP16(dst, src);
        }
    } else {
        const int pc = (c - 32) * 32;
        // A: pw values
#pragma unroll
        for (int it = 0; it < 8; it++) {
            int id = tid + it * 256;
            int r = id >> 3, f4 = id & 7;
            int bq = r >> 6, a = r & 63; if (a >= cx.n_ants) a = cx.n_ants - 1;
            unsigned long long src = cx.pw_g +
                (((size_t)(cx.b0 + bq) * cx.n_ants + a) * PW + pc + f4 * 4) * 4ull;
            CP16(stg + (uint32_t)(r * (APAD * 4) + f4 * 16), src);
        }
        // B: W1p into Bh
#pragma unroll
        for (int it = 0; it < 4; it++) {
            int id = tid + it * 256;
            int n = id >> 3, f4 = id & 7;
            unsigned long long src = cx.w1t_g +
                ((size_t)n * KSEG + 2048 + pc + f4 * 4) * 4ull;
            CP16(stg + OFF_BH + (uint32_t)(n * (APAD * 4) + f4 * 16), src);
        }
    }
}

__global__ __launch_bounds__(256)
void pair_mma_kernel(const float* __restrict__ all_m,
                     const float* __restrict__ m_b,
                     const float* __restrict__ pw,
                     const void*  __restrict__ top_idx,
                     const float* __restrict__ rough,
                     const float* __restrict__ W_out,
                     const float* __restrict__ b_out,
                     float* __restrict__ out,
                     int n_ants) {
    extern __shared__ char smem[];
    const uint32_t sbase = smem_u32(smem);
    const int tid  = threadIdx.x;
    const int lane = tid & 31;
    const int wid  = tid >> 5;
    const int t    = lane & 3;        // k lane within quad
    const int q    = lane >> 2;       // row lane
    const int b0   = blockIdx.x * 4;
    const int bq   = wid >> 1;        // this warp's batch quarter (rows 32w..32w+31 -> b0+bq)

    int*   idx_s   = (int*)(smem + OFF_IDX);
    float* wout_s  = (float*)(smem + OFF_WOUT);
    float* aproj_s = (float*)(smem + OFF_APROJ);
    float* am_s    = (float*)(smem + OFF_AM);

    StageCtx cx;
    cx.all_m_g = to_global(all_m);
    cx.w1t_g   = to_global(g_W1T);
    cx.pw_g    = to_global(pw);
    cx.b0 = b0; cx.n_ants = n_ants;

    // ---- idx staging (needed by stage_chunk) ----
    {
        int a = tid & 63; if (a >= n_ants) a = n_ants - 1;
        idx_s[tid] = load_idx(top_idx, (size_t)(b0 + (tid >> 6)) * n_ants + a, g_idx64);
    }
    __syncthreads();

    // ---- prologue: stage chunk 0 + am tile; plain-load wout/aproj ----
    stage_chunk(0, smem, sbase, idx_s, cx, tid);
    {
        unsigned long long mbg = to_global(m_b);
#pragma unroll
        for (int it = 0; it < 4; it++) {
            int id = tid + it * 256;           // 1024 float4 = 4096 floats
            int bqi = id >> 8, e4 = id & 255;
            CP16(sbase + OFF_AM + (uint32_t)id * 16,
                 mbg + ((size_t)(b0 + bqi) * EMB + e4 * 4) * 4ull);
        }
    }
    CP_COMMIT();
    if (tid < 128) wout_s[tid] = W_out[tid];
    aproj_s[tid]       = g_Aproj[(size_t)(b0 + (tid >> 7)) * HID + (tid & 127)];
    aproj_s[tid + 256] = g_Aproj[(size_t)(b0 + 2 + (tid >> 7)) * HID + (tid & 127)];

    // ---- accumulators: warp tile 32 x 128 -> 2 m-frags x 16 n-frags ----
    float acc[2][16][4];
#pragma unroll
    for (int i = 0; i < 2; i++)
#pragma unroll
        for (int nf = 0; nf < 16; nf++)
#pragma unroll
            for (int r = 0; r < 4; r++) acc[i][nf][r] = 0.f;

    for (int c = 0; c < NCHUNK; c++) {
        if (c + 1 < NCHUNK) {
            stage_chunk(c + 1, smem, sbase, idx_s, cx, tid);
            CP_COMMIT();
            CP_WAIT1();
        } else {
            CP_WAIT0();
        }
        __syncthreads();

        const float* Ab = (const float*)(smem + OFF_STAGE + (c & 1) * STAGE_B);
        const float* Bh = (const float*)(smem + OFF_STAGE + (c & 1) * STAGE_B + OFF_BH);
        const float* Bs = (const float*)(smem + OFF_STAGE + (c & 1) * STAGE_B + OFF_BS);
        const bool has_sim = (c < 32);
        const int  ec = c * 32;   // only meaningful when has_sim

#pragma unroll
        for (int j = 0; j < 4; j++) {         // k8 steps over the 32-wide chunk
            const int k0 = j * 8;
            // A fragments (bm / pw), rows m = 32*wid + 16i + q (+8)
            uint32_t a_[2][4];
#pragma unroll
            for (int i = 0; i < 2; i++) {
                const float* ap = Ab + (size_t)(wid * 32 + 16 * i + q) * APAD + k0 + t;
                a_[i][0] = __float_as_uint(ap[0]);
                a_[i][1] = __float_as_uint(ap[8 * APAD]);
                a_[i][2] = __float_as_uint(ap[4]);
                a_[i][3] = __float_as_uint(ap[8 * APAD + 4]);
            }
            uint32_t as_[2][4];
            if (has_sim) {
                float am_lo = am_s[bq * EMB + ec + k0 + t];
                float am_hi = am_s[bq * EMB + ec + k0 + 4 + t];
#pragma unroll
                for (int i = 0; i < 2; i++) {
                    as_[i][0] = __float_as_uint(__uint_as_float(a_[i][0]) * am_lo);
                    as_[i][1] = __float_as_uint(__uint_as_float(a_[i][1]) * am_lo);
                    as_[i][2] = __float_as_uint(__uint_as_float(a_[i][2]) * am_hi);
                    as_[i][3] = __float_as_uint(__uint_as_float(a_[i][3]) * am_hi);
                }
            }
#pragma unroll
            for (int nf = 0; nf < 16; nf++) {
                const float* bp = Bh + (size_t)(nf * 8 + q) * APAD + k0 + t;
                uint32_t b0r = __float_as_uint(bp[0]);
                uint32_t b1r = __float_as_uint(bp[4]);
                mma_tf32(acc[0][nf], a_[0][0], a_[0][1], a_[0][2], a_[0][3], b0r, b1r);
                mma_tf32(acc[1][nf], a_[1][0], a_[1][1], a_[1][2], a_[1][3], b0r, b1r);
                if (has_sim) {
                    const float* sp = Bs + (size_t)(nf * 8 + q) * APAD + k0 + t;
                    uint32_t s0r = __float_as_uint(sp[0]);
                    uint32_t s1r = __float_as_uint(sp[4]);
                    mma_tf32(acc[0][nf], as_[0][0], as_[0][1], as_[0][2], as_[0][3], s0r, s1r);
                    mma_tf32(acc[1][nf], as_[1][0], as_[1][1], as_[1][2], as_[1][3], s0r, s1r);
                }
            }
        }
        __syncthreads();
    }

    // ---- epilogue: h = D + aproj; LeakyReLU; dot W_out; + rough + b_out ----
    const float bo = b_out[0];
    const float* apq = aproj_s + bq * 128;
#pragma unroll
    for (int i = 0; i < 2; i++) {
        float s_lo = 0.f, s_hi = 0.f;
#pragma unroll
        for (int nf = 0; nf < 16; nf++) {
            int n0 = nf * 8 + 2 * t, n1 = n0 + 1;
            float w0 = wout_s[n0], w1 = wout_s[n1];
            float ap0 = apq[n0], ap1 = apq[n1];
            float h;
            h = acc[i][nf][0] + ap0; h = fmaxf(h, 0.f) + 0.01f * fminf(h, 0.f); s_lo += h * w0;
            h = acc[i][nf][1] + ap1; h = fmaxf(h, 0.f) + 0.01f * fminf(h, 0.f); s_lo += h * w1;
            h = acc[i][nf][2] + ap0; h = fmaxf(h, 0.f) + 0.01f * fminf(h, 0.f); s_hi += h * w0;
            h = acc[i][nf][3] + ap1; h = fmaxf(h, 0.f) + 0.01f * fminf(h, 0.f); s_hi += h * w1;
        }
        s_lo += __shfl_xor_sync(0xffffffffu, s_lo, 1);
        s_lo += __shfl_xor_sync(0xffffffffu, s_lo, 2);
        s_hi += __shfl_xor_sync(0xffffffffu, s_hi, 1);
        s_hi += __shfl_xor_sync(0xffffffffu, s_hi, 2);
        if (t == 0) {
            int r_lo = wid * 32 + 16 * i + q;
#pragma unroll
            for (int h2 = 0; h2 < 2; h2++) {
                int r = r_lo + 8 * h2;
                float sc = h2 ? s_hi : s_lo;
                int a = r & 63, bg = b0 + (r >> 6);
                if (a < n_ants)
                    out[(size_t)bg * (n_ants + 1) + 1 + a] =
                        rough[(size_t)bg * n_ants + a] + bo + sc;
                if (a == 0)
                    out[(size_t)bg * (n_ants + 1)] = EPSV;
            }
        }
    }
}

// -------------------- launch --------------------
extern "C" void kernel_launch(void* const* d_in, const int* in_sizes, int n_in,
                              void* d_out, int out_size) {
    const float* all_m = (const float*)d_in[0];
    const float* m_b   = (const float*)d_in[1];
    const float* pw    = (const float*)d_in[2];
    const void*  idx   = d_in[3];
    const float* rough = (const float*)d_in[4];
    const float* W1    = (const float*)d_in[5];
    const float* b1    = (const float*)d_in[6];
    const float* Wo    = (const float*)d_in[7];
    const float* bo    = (const float*)d_in[8];
    float* out = (float*)d_out;

    const int batch  = in_sizes[1] / EMB;     // 512
    const int n_ants = in_sizes[3] / batch;   // 50

    cudaFuncSetAttribute(pair_mma_kernel,
                         cudaFuncAttributeMaxDynamicSharedMemorySize, SMEM_TOTAL);

    detect_idx_kernel<<<1, 1>>>((const unsigned*)idx, in_sizes[3]);
    transpose_w1_kernel<<<dim3(KSEG / 32, HID / 32), 256>>>(W1);
    aproj_kernel<<<(batch + 31) / 32, 256>>>(m_b, batch, W1, b1);
    pair_mma_kernel<<<batch / 4, 256, SMEM_TOTAL>>>(all_m, m_b, pw, idx, rough,
                                                    Wo, bo, out, n_ants);
}

// round 6
// speedup vs baseline: 4.0145x; 1.9633x over previous
#include <cuda_runtime.h>
#include <cstdint>

#define EMB    1024
#define HID    128
#define PW     64
#define KSEG   2112          // g_W1T cols: bm(1024) + sim(1024) + pw(64) = W1 rows [1024,3136)
#define NCHUNK 34            // 32 e-chunks (K=32, sim folded into B) + 2 pw chunks (K=32)
#define EPSV   1e-7f

// -------------------- device scratch (no allocs allowed) --------------------
__device__ float g_W1T[HID * KSEG];   // W1T[n][k] = tf32_rna(W1[1024+k][n])
__device__ int   g_idx64;

// -------------------- helpers --------------------
__device__ __forceinline__ uint32_t smem_u32(const void* p) {
    uint32_t a;
    asm("{ .reg .u64 t; cvta.to.shared.u64 t, %1; cvt.u32.u64 %0, t; }" : "=r"(a) : "l"(p));
    return a;
}
__device__ __forceinline__ unsigned long long to_global(const void* p) {
    unsigned long long g;
    asm("cvta.to.global.u64 %0, %1;" : "=l"(g) : "l"(p));
    return g;
}
#define CP16(dst_s32, src_g64) \
    asm volatile("cp.async.cg.shared.global [%0], [%1], 16;" :: "r"(dst_s32), "l"(src_g64) : "memory")
#define CP_COMMIT() asm volatile("cp.async.commit_group;" ::: "memory")
#define CP_WAIT1()  asm volatile("cp.async.wait_group 1;" ::: "memory")

__device__ __forceinline__ void mma_tf32(float c[4], uint32_t a0, uint32_t a1, uint32_t a2, uint32_t a3,
                                         uint32_t b0, uint32_t b1) {
    asm volatile("mma.sync.aligned.m16n8k8.row.col.f32.tf32.tf32.f32 "
                 "{%0,%1,%2,%3}, {%4,%5,%6,%7}, {%8,%9}, {%0,%1,%2,%3};"
                 : "+f"(c[0]), "+f"(c[1]), "+f"(c[2]), "+f"(c[3])
                 : "r"(a0), "r"(a1), "r"(a2), "r"(a3), "r"(b0), "r"(b1));
}

// -------------------- idx dtype detection --------------------
__global__ void detect_idx_kernel(const unsigned* __restrict__ w, int n_words) {
    unsigned acc = 0;
    int m = n_words < 256 ? n_words : 256;
    for (int i = 1; i < m; i += 2) acc |= w[i];
    g_idx64 = (acc == 0u) ? 1 : 0;
}
__device__ __forceinline__ int load_idx(const void* p, size_t pos, int is64) {
    return is64 ? (int)((const long long*)p)[pos] : ((const int*)p)[pos];
}

// -------------------- W1 transpose + tf32 round: g_W1T[n][k] = rna(W1[1024+k][n]) ----------------
__global__ __launch_bounds__(256)
void transpose_w1_kernel(const float* __restrict__ W1) {
    __shared__ float s[32][33];
    const int kb = blockIdx.x * 32, nb = blockIdx.y * 32;
    const int tx = threadIdx.x & 31, ty = threadIdx.x >> 5;
#pragma unroll
    for (int j = 0; j < 4; j++) {
        int k = ty + 8 * j;
        s[k][tx] = W1[(size_t)(1024 + kb + k) * HID + nb + tx];
    }
    __syncthreads();
#pragma unroll
    for (int j = 0; j < 4; j++) {
        int y = ty + 8 * j;
        float v = s[tx][y];
        uint32_t tv;
        asm("cvt.rna.tf32.f32 %0, %1;" : "=r"(tv) : "f"(v));
        g_W1T[(size_t)(nb + y) * KSEG + kb + tx] = __uint_as_float(tv);
    }
}

// -------------------- fused pair kernel --------------------
// Block: 4 batch rows -> M=256 (4 x 64 padded ants), N=128 hidden, 512 threads / 16 warps.
// Warp (mi = wid&7, nh = wid>>3): rows [32mi, 32mi+32), cols [64nh, 64nh+64). bq = mi>>1.
// Per e-chunk: B''_q = W1b + am_q (.) W1s computed in smem; single MMA stream.
// aproj (am @ W1[0:1024] + b1) interleaved into the mainloop, applied in epilogue.
//
// smem map (bytes):
#define OFF_IDX    0                     // 256 ints
#define OFF_WOUT   1024                  // 128 f
#define OFF_APROJ  1536                  // 512 f
#define OFF_STAGE  4096
#define ST_A       0                     // 256 rows x 36 f (144B rows)
#define ST_AM      36864                 // 4 x 36 f
#define ST_WB      37440                 // 128 x 36 f
#define ST_WS      (37440 + 18432)       // 128 x 36 f
#define STAGE_B    (37440 + 36864)       // 74304
#define OFF_BPP    (OFF_STAGE + 2 * STAGE_B)       // 152704; B'': 4 x 128 x 36 f = 73728
#define SMEM_TOTAL (OFF_BPP + 4 * 128 * 36 * 4)    // 226432 <= 232448

struct StageCtx {
    unsigned long long all_m_g, w1t_g, pw_g, mb_g;
    int b0, n_ants;
};

__device__ __forceinline__ void stage_chunk(int c, uint32_t sbase,
                                            const int* idx_s, const StageCtx& cx, int tid) {
    const uint32_t stg = sbase + OFF_STAGE + (uint32_t)(c & 1) * STAGE_B;
    if (c < 32) {
        const int ec = c * 32;
        // A: gathered bm rows [256][32]
#pragma unroll
        for (int it = 0; it < 4; it++) {
            int id = tid + it * 512;
            int r = id >> 3, f4 = id & 7;
            unsigned long long src = cx.all_m_g + ((size_t)idx_s[r] * EMB + ec + f4 * 4) * 4ull;
            CP16(stg + ST_A + (uint32_t)(r * 144 + f4 * 16), src);
        }
        // AM: am chunk [4][32]
        if (tid < 32) {
            int q = tid >> 3, f4 = tid & 7;
            unsigned long long src = cx.mb_g + ((size_t)(cx.b0 + q) * EMB + ec + f4 * 4) * 4ull;
            CP16(stg + ST_AM + (uint32_t)(q * 144 + f4 * 16), src);
        }
        // B: W1b and W1s chunks [128][32] each
#pragma unroll
        for (int it = 0; it < 4; it++) {
            int id = tid + it * 512;
            int seg = id >> 10, n = (id >> 3) & 127, f4 = id & 7;
            unsigned long long src = cx.w1t_g +
                ((size_t)n * KSEG + (seg ? 1024 + ec : ec) + f4 * 4) * 4ull;
            CP16(stg + (seg ? ST_WS : ST_WB) + (uint32_t)(n * 144 + f4 * 16), src);
        }
    } else {
        const int pc = (c - 32) * 32;
        // A: pw values [256][32]
#pragma unroll
        for (int it = 0; it < 4; it++) {
            int id = tid + it * 512;
            int r = id >> 3, f4 = id & 7;
            int bq = r >> 6, a = r & 63; if (a >= cx.n_ants) a = cx.n_ants - 1;
            unsigned long long src = cx.pw_g +
                (((size_t)(cx.b0 + bq) * cx.n_ants + a) * PW + pc + f4 * 4) * 4ull;
            CP16(stg + ST_A + (uint32_t)(r * 144 + f4 * 16), src);
        }
        // B: W1p chunk into WB region
#pragma unroll
        for (int it = 0; it < 2; it++) {
            int id = tid + it * 512;
            int n = id >> 3, f4 = id & 7;
            unsigned long long src = cx.w1t_g + ((size_t)n * KSEG + 2048 + pc + f4 * 4) * 4ull;
            CP16(stg + ST_WB + (uint32_t)(n * 144 + f4 * 16), src);
        }
    }
}

__global__ __launch_bounds__(512)
void pair_mma_kernel(const float* __restrict__ all_m,
                     const float* __restrict__ m_b,
                     const float* __restrict__ pw,
                     const void*  __restrict__ top_idx,
                     const float* __restrict__ rough,
                     const float* __restrict__ W1,
                     const float* __restrict__ b1,
                     const float* __restrict__ W_out,
                     const float* __restrict__ b_out,
                     float* __restrict__ out,
                     int n_ants) {
    extern __shared__ char smem[];
    const uint32_t sbase = smem_u32(smem);
    const int tid  = threadIdx.x;
    const int lane = tid & 31;
    const int wid  = tid >> 5;
    const int t    = lane & 3;       // k lane within quad
    const int q    = lane >> 2;      // row/col lane (0..7)
    const int b0   = blockIdx.x * 4;
    const int mi   = wid & 7;        // m-tile: rows [32mi, 32mi+32)
    const int nh   = wid >> 3;       // n-half: cols [64nh, 64nh+64)
    const int bq   = mi >> 1;        // batch quarter of this warp's rows

    int*   idx_s   = (int*)(smem + OFF_IDX);
    float* wout_s  = (float*)(smem + OFF_WOUT);
    float* aproj_s = (float*)(smem + OFF_APROJ);

    StageCtx cx;
    cx.all_m_g = to_global(all_m);
    cx.w1t_g   = to_global(g_W1T);
    cx.pw_g    = to_global(pw);
    cx.mb_g    = to_global(m_b);
    cx.b0 = b0; cx.n_ants = n_ants;

    // ---- idx staging (needed by stage_chunk) ----
    if (tid < 256) {
        int a = tid & 63; if (a >= n_ants) a = n_ants - 1;
        idx_s[tid] = load_idx(top_idx, (size_t)(b0 + (tid >> 6)) * n_ants + a, g_idx64);
    }
    if (tid < 128) wout_s[tid] = W_out[tid];
    __syncthreads();

    stage_chunk(0, sbase, idx_s, cx, tid); CP_COMMIT();
    stage_chunk(1, sbase, idx_s, cx, tid); CP_COMMIT();

    // accumulators: 2 m-frags x 8 n-frags x 4
    float acc[2][8][4];
#pragma unroll
    for (int i = 0; i < 2; i++)
#pragma unroll
        for (int nf = 0; nf < 8; nf++)
#pragma unroll
            for (int r = 0; r < 4; r++) acc[i][nf][r] = 0.f;

    // aproj accumulator: thread owns (abq = tid>>7, an = tid&127)
    const int abq = tid >> 7, an = tid & 127;
    const float* ap_w  = W1 + an;
    const float* ap_am = m_b + (size_t)(b0 + abq) * EMB;
    float aproj_acc = 0.f;

    const int rb = mi * 32, nb = nh * 64;

    for (int c = 0; c < NCHUNK; c++) {
        CP_WAIT1();
        __syncthreads();                         // stage(c) ready; prior MMA done reading B''

        const uint32_t stg = sbase + OFF_STAGE + (uint32_t)(c & 1) * STAGE_B;
        if (c < 32) {
            // B''_q[n][k] = W1b[n][k] + am_q[k] * W1s[n][k]
            const float4* wb  = (const float4*)(smem + (c & 1) * STAGE_B + OFF_STAGE + ST_WB + an * 144);
            const float4* ws  = (const float4*)(smem + (c & 1) * STAGE_B + OFF_STAGE + ST_WS + an * 144);
            const float4* amv = (const float4*)(smem + (c & 1) * STAGE_B + OFF_STAGE + ST_AM + abq * 144);
            float4* dst = (float4*)(smem + OFF_BPP + (size_t)(abq * 128 + an) * 144);
#pragma unroll
            for (int f = 0; f < 8; f++) {
                float4 bvv = wb[f], sv = ws[f], av = amv[f];
                float4 o;
                o.x = bvv.x + av.x * sv.x; o.y = bvv.y + av.y * sv.y;
                o.z = bvv.z + av.z * sv.z; o.w = bvv.w + av.w * sv.w;
                dst[f] = o;
            }
        }
        __syncthreads();                         // B'' ready

        const float* Ab = (const float*)(smem + OFF_STAGE + (c & 1) * STAGE_B + ST_A);
        const float* Bp = (c < 32)
            ? (const float*)(smem + OFF_BPP) + (size_t)bq * 128 * 36
            : (const float*)(smem + OFF_STAGE + (c & 1) * STAGE_B + ST_WB);

#pragma unroll
        for (int j = 0; j < 4; j++) {
            const int k0 = j * 8;
            uint32_t a_[2][4];
#pragma unroll
            for (int i = 0; i < 2; i++) {
                const float* ap = Ab + (size_t)(rb + 16 * i + q) * 36 + k0 + t;
                a_[i][0] = __float_as_uint(ap[0]);
                a_[i][1] = __float_as_uint(ap[8 * 36]);
                a_[i][2] = __float_as_uint(ap[4]);
                a_[i][3] = __float_as_uint(ap[8 * 36 + 4]);
            }
#pragma unroll
            for (int nf = 0; nf < 8; nf++) {
                const float* bp = Bp + (size_t)(nb + nf * 8 + q) * 36 + k0 + t;
                uint32_t b0r = __float_as_uint(bp[0]);
                uint32_t b1r = __float_as_uint(bp[4]);
                mma_tf32(acc[0][nf], a_[0][0], a_[0][1], a_[0][2], a_[0][3], b0r, b1r);
                mma_tf32(acc[1][nf], a_[1][0], a_[1][1], a_[1][2], a_[1][3], b0r, b1r);
            }
        }

        // interleaved aproj: 32 k-steps per e-chunk (global reads hit L1/L2)
        if (c < 32) {
            const float* wrow = ap_w + (size_t)(c * 32) * HID;
            const float* amr  = ap_am + c * 32;
#pragma unroll 8
            for (int kk = 0; kk < 32; kk++)
                aproj_acc += __ldg(amr + kk) * __ldg(wrow + (size_t)kk * HID);
        }
        __syncthreads();                         // MMA done reading A(c); safe to restage buffer (c&1)

        if (c + 2 < NCHUNK) stage_chunk(c + 2, sbase, idx_s, cx, tid);
        CP_COMMIT();                             // empty groups keep wait_group numbering stable
    }

    // ---- epilogue ----
    aproj_s[tid] = aproj_acc + b1[an];           // tid == abq*128+an
    __syncthreads();

    float* part = (float*)(smem + OFF_BPP);      // reuse B'' as [256][2] scratch
    const float  bo  = __ldg(b_out);
    const float* apq = aproj_s + bq * 128;
#pragma unroll
    for (int i = 0; i < 2; i++) {
        float s0 = 0.f, s1 = 0.f;                // rows rb+16i+q and rb+16i+q+8
#pragma unroll
        for (int nf = 0; nf < 8; nf++) {
            int n0 = nb + nf * 8 + 2 * t, n1 = n0 + 1;
            float w0 = wout_s[n0], w1 = wout_s[n1];
            float ap0 = apq[n0], ap1 = apq[n1];
            float h;
            h = acc[i][nf][0] + ap0; h = fmaxf(h, 0.f) + 0.01f * fminf(h, 0.f); s0 += h * w0;
            h = acc[i][nf][1] + ap1; h = fmaxf(h, 0.f) + 0.01f * fminf(h, 0.f); s0 += h * w1;
            h = acc[i][nf][2] + ap0; h = fmaxf(h, 0.f) + 0.01f * fminf(h, 0.f); s1 += h * w0;
            h = acc[i][nf][3] + ap1; h = fmaxf(h, 0.f) + 0.01f * fminf(h, 0.f); s1 += h * w1;
        }
        s0 += __shfl_xor_sync(0xffffffffu, s0, 1);
        s0 += __shfl_xor_sync(0xffffffffu, s0, 2);
        s1 += __shfl_xor_sync(0xffffffffu, s1, 1);
        s1 += __shfl_xor_sync(0xffffffffu, s1, 2);
        if (t == 0) {
            part[(rb + 16 * i + q) * 2 + nh]     = s0;
            part[(rb + 16 * i + q + 8) * 2 + nh] = s1;
        }
    }
    __syncthreads();

    if (tid < 256) {
        float sc = part[tid * 2] + part[tid * 2 + 1];
        int a = tid & 63, bg = b0 + (tid >> 6);
        if (a < n_ants)
            out[(size_t)bg * (n_ants + 1) + 1 + a] =
                rough[(size_t)bg * n_ants + a] + bo + sc;
        if (a == 0) out[(size_t)bg * (n_ants + 1)] = EPSV;
    }
}

// -------------------- launch --------------------
extern "C" void kernel_launch(void* const* d_in, const int* in_sizes, int n_in,
                              void* d_out, int out_size) {
    const float* all_m = (const float*)d_in[0];
    const float* m_b   = (const float*)d_in[1];
    const float* pw    = (const float*)d_in[2];
    const void*  idx   = d_in[3];
    const float* rough = (const float*)d_in[4];
    const float* W1    = (const float*)d_in[5];
    const float* b1    = (const float*)d_in[6];
    const float* Wo    = (const float*)d_in[7];
    const float* bo    = (const float*)d_in[8];
    float* out = (float*)d_out;

    const int batch  = in_sizes[1] / EMB;     // 512
    const int n_ants = in_sizes[3] / batch;   // 50

    cudaFuncSetAttribute(pair_mma_kernel,
                         cudaFuncAttributeMaxDynamicSharedMemorySize, SMEM_TOTAL);

    detect_idx_kernel<<<1, 1>>>((const unsigned*)idx, in_sizes[3]);
    transpose_w1_kernel<<<dim3(KSEG / 32, HID / 32), 256>>>(W1);
    pair_mma_kernel<<<batch / 4, 512, SMEM_TOTAL>>>(all_m, m_b, pw, idx, rough,
                                                    W1, b1, Wo, bo, out, n_ants);
}

// round 8
// speedup vs baseline: 4.7803x; 1.1907x over previous
#include <cuda_runtime.h>
#include <cstdint>

#define EMB    1024
#define HID    128
#define PW     64
#define KSEG   2112          // g_W1T cols: bm(1024) + sim(1024) + pw(64) = W1 rows [1024,3136)
#define NCHUNK 34            // 32 e-chunks (K=32, sim folded into B) + 2 pw chunks
#define EPSV   1e-7f

// -------------------- device scratch (no allocs allowed) --------------------
__device__ float g_W1T[HID * KSEG];   // g_W1T[n][32-blk b][perm pos] = tf32(W1[1024+32b+k][n])
__device__ int   g_idx64;

// -------------------- helpers --------------------
__device__ __forceinline__ uint32_t smem_u32(const void* p) {
    uint32_t a;
    asm("{ .reg .u64 t; cvta.to.shared.u64 t, %1; cvt.u32.u64 %0, t; }" : "=r"(a) : "l"(p));
    return a;
}
__device__ __forceinline__ unsigned long long to_global(const void* p) {
    unsigned long long g;
    asm("cvta.to.global.u64 %0, %1;" : "=l"(g) : "l"(p));
    return g;
}
#define CP16(dst_s32, src_g64) \
    asm volatile("cp.async.cg.shared.global [%0], [%1], 16;" :: "r"(dst_s32), "l"(src_g64) : "memory")
#define CP_COMMIT() asm volatile("cp.async.commit_group;" ::: "memory")
#define CP_WAIT1()  asm volatile("cp.async.wait_group 1;" ::: "memory")

__device__ __forceinline__ void mma_tf32(float c[4], uint32_t a0, uint32_t a1, uint32_t a2, uint32_t a3,
                                         uint32_t b0, uint32_t b1) {
    asm volatile("mma.sync.aligned.m16n8k8.row.col.f32.tf32.tf32.f32 "
                 "{%0,%1,%2,%3}, {%4,%5,%6,%7}, {%8,%9}, {%0,%1,%2,%3};"
                 : "+f"(c[0]), "+f"(c[1]), "+f"(c[2]), "+f"(c[3])
                 : "r"(a0), "r"(a1), "r"(a2), "r"(a3), "r"(b0), "r"(b1));
}
__device__ __forceinline__ int load_idx(const void* p, size_t pos, int is64) {
    return is64 ? (int)((const long long*)p)[pos] : ((const int*)p)[pos];
}

// -------------------- W1 transpose + tf32 round + t-major permute (+ idx detect) ----------------
// g_W1T[n][kb + perm(k)] = rna(W1[1024+kb+k][n]);  perm(k) = 8*(k&3) + 2*(k>>3) + ((k>>2)&1)
__global__ __launch_bounds__(256)
void transpose_w1_kernel(const float* __restrict__ W1,
                         const unsigned* __restrict__ idxw, int n_words) {
    __shared__ float s[32][33];
    const int kb = blockIdx.x * 32, nb = blockIdx.y * 32;
    const int tx = threadIdx.x & 31, ty = threadIdx.x >> 5;
    if (blockIdx.x == 0 && blockIdx.y == 0 && threadIdx.x == 0) {
        unsigned acc = 0;
        int m = n_words < 256 ? n_words : 256;
        for (int i = 1; i < m; i += 2) acc |= idxw[i];
        g_idx64 = (acc == 0u) ? 1 : 0;
    }
#pragma unroll
    for (int j = 0; j < 4; j++) {
        int k = ty + 8 * j;
        s[k][tx] = W1[(size_t)(1024 + kb + k) * HID + nb + tx];
    }
    __syncthreads();
#pragma unroll
    for (int j = 0; j < 4; j++) {
        int y = ty + 8 * j;
        float v = s[tx][y];
        uint32_t tv;
        asm("cvt.rna.tf32.f32 %0, %1;" : "=r"(tv) : "f"(v));
        int pk = 8 * (tx & 3) + 2 * (tx >> 3) + ((tx >> 2) & 1);
        g_W1T[(size_t)(nb + y) * KSEG + kb + pk] = __uint_as_float(tv);
    }
}

// -------------------- fused pair kernel --------------------
// Block: 4 batch rows -> M=256, N=128, 512 threads / 16 warps.
// Warp (mi = wid&3, nh = wid>>2): rows [64mi, 64mi+64), cols [32nh, 32nh+32); bq == mi.
// B'' = WB + am (.) WS folded IN REGISTERS per warp (no smem B'' phase).
// aproj (am @ W1[0:1024] + b1) interleaved via coalesced global loads.
#define OFF_IDX    0                     // 256 ints
#define OFF_WOUT   1024                  // 128 f
#define OFF_APROJ  1536                  // 512 f
#define OFF_STAGE  4096
#define ST_A       0                     // 256 rows x 36 f (144B rows), plain k layout
#define ST_AM      36864                 // 4 x 36 f, plain
#define ST_WB      37440                 // 128 x 36 f, t-major permuted (from g_W1T)
#define ST_WS      55872                 // 128 x 36 f, t-major permuted
#define STAGE_B    74304
#define SMEM_TOTAL (OFF_STAGE + 2 * STAGE_B)   // 152704

struct StageCtx {
    unsigned long long all_m_g, w1t_g, pw_g, mb_g;
    int b0, n_ants;
};

__device__ __forceinline__ void stage_chunk(int c, uint32_t sbase,
                                            const int* idx_s, const StageCtx& cx, int tid) {
    const uint32_t stg = sbase + OFF_STAGE + (uint32_t)(c & 1) * STAGE_B;
    if (c < 32) {
        const int ec = c * 32;
#pragma unroll
        for (int it = 0; it < 4; it++) {       // A: gathered bm rows [256][32]
            int id = tid + it * 512;
            int r = id >> 3, f4 = id & 7;
            unsigned long long src = cx.all_m_g + ((size_t)idx_s[r] * EMB + ec + f4 * 4) * 4ull;
            CP16(stg + ST_A + (uint32_t)(r * 144 + f4 * 16), src);
        }
        if (tid < 32) {                        // AM: am chunk [4][32]
            int q = tid >> 3, f4 = tid & 7;
            unsigned long long src = cx.mb_g + ((size_t)(cx.b0 + q) * EMB + ec + f4 * 4) * 4ull;
            CP16(stg + ST_AM + (uint32_t)(q * 144 + f4 * 16), src);
        }
#pragma unroll
        for (int it = 0; it < 4; it++) {       // WB / WS (permuted in gmem)
            int id = tid + it * 512;
            int seg = id >> 10, n = (id >> 3) & 127, f4 = id & 7;
            unsigned long long src = cx.w1t_g +
                ((size_t)n * KSEG + (seg ? 1024 + ec : ec) + f4 * 4) * 4ull;
            CP16(stg + (seg ? ST_WS : ST_WB) + (uint32_t)(n * 144 + f4 * 16), src);
        }
    } else {
        const int pc = (c - 32) * 32;
#pragma unroll
        for (int it = 0; it < 4; it++) {       // A: pw values [256][32]
            int id = tid + it * 512;
            int r = id >> 3, f4 = id & 7;
            int bq = r >> 6, a = r & 63; if (a >= cx.n_ants) a = cx.n_ants - 1;
            unsigned long long src = cx.pw_g +
                (((size_t)(cx.b0 + bq) * cx.n_ants + a) * PW + pc + f4 * 4) * 4ull;
            CP16(stg + ST_A + (uint32_t)(r * 144 + f4 * 16), src);
        }
#pragma unroll
        for (int it = 0; it < 2; it++) {       // B: W1p (permuted) into WB region
            int id = tid + it * 512;
            int n = id >> 3, f4 = id & 7;
            unsigned long long src = cx.w1t_g + ((size_t)n * KSEG + 2048 + pc + f4 * 4) * 4ull;
            CP16(stg + ST_WB + (uint32_t)(n * 144 + f4 * 16), src);
        }
    }
}

__global__ __launch_bounds__(512)
void pair_mma_kernel(const float* __restrict__ all_m,
                     const float* __restrict__ m_b,
                     const float* __restrict__ pw,
                     const void*  __restrict__ top_idx,
                     const float* __restrict__ rough,
                     const float* __restrict__ W1,
                     const float* __restrict__ b1,
                     const float* __restrict__ W_out,
                     const float* __restrict__ b_out,
                     float* __restrict__ out,
                     int n_ants) {
    extern __shared__ char smem[];
    const uint32_t sbase = smem_u32(smem);
    const int tid  = threadIdx.x;
    const int lane = tid & 31;
    const int wid  = tid >> 5;
    const int t    = lane & 3;       // k lane within quad
    const int q    = lane >> 2;      // row/col lane (0..7)
    const int b0   = blockIdx.x * 4;
    const int mi   = wid & 3;        // m-tile: rows [64mi, 64mi+64); == bq
    const int nh   = wid >> 2;       // n-quarter: cols [32nh, 32nh+32)
    const int rb   = mi * 64, nb = nh * 32;

    int*   idx_s   = (int*)(smem + OFF_IDX);
    float* wout_s  = (float*)(smem + OFF_WOUT);
    float* aproj_s = (float*)(smem + OFF_APROJ);

    StageCtx cx;
    cx.all_m_g = to_global(all_m);
    cx.w1t_g   = to_global(g_W1T);
    cx.pw_g    = to_global(pw);
    cx.mb_g    = to_global(m_b);
    cx.b0 = b0; cx.n_ants = n_ants;

    if (tid < 256) {
        int a = tid & 63; if (a >= n_ants) a = n_ants - 1;
        idx_s[tid] = load_idx(top_idx, (size_t)(b0 + (tid >> 6)) * n_ants + a, g_idx64);
    }
    if (tid < 128) wout_s[tid] = W_out[tid];
    __syncthreads();

    stage_chunk(0, sbase, idx_s, cx, tid); CP_COMMIT();
    stage_chunk(1, sbase, idx_s, cx, tid); CP_COMMIT();

    // accumulators: 4 m-frags x 4 n-frags x 4
    float acc[4][4][4];
#pragma unroll
    for (int i = 0; i < 4; i++)
#pragma unroll
        for (int nf = 0; nf < 4; nf++)
#pragma unroll
            for (int r = 0; r < 4; r++) acc[i][nf][r] = 0.f;

    // aproj accumulator: thread owns (abq = tid>>7, an = tid&127); coalesced W1 rows
    const int abq = tid >> 7, an = tid & 127;
    const float* ap_w  = W1 + an;
    const float* ap_am = m_b + (size_t)(b0 + abq) * EMB;
    float aproj_acc = 0.f;

    for (int c = 0; c < NCHUNK; c++) {
        CP_WAIT1();
        __syncthreads();                       // stage(c) ready

        const char*  stp = smem + OFF_STAGE + (c & 1) * STAGE_B;
        const float* Ab  = (const float*)(stp + ST_A);
        const float* amr = (const float*)(stp + ST_AM) + mi * 36;
        const bool has_sim = (c < 32);

#pragma unroll
        for (int h2 = 0; h2 < 2; h2++) {       // two k16 halves per chunk
            float bpp[4][4];
            float am0, am1, am2, am3;
            if (has_sim) {
                am0 = amr[16 * h2 + t];        // (jp=0, b0)
                am1 = amr[16 * h2 + 4 + t];    // (jp=0, b1)
                am2 = amr[16 * h2 + 8 + t];    // (jp=1, b0)
                am3 = amr[16 * h2 + 12 + t];   // (jp=1, b1)
            }
#pragma unroll
            for (int nf = 0; nf < 4; nf++) {
                int n = nb + nf * 8 + q;
                float4 wb4 = *(const float4*)(stp + ST_WB + n * 144 + t * 32 + h2 * 16);
                if (has_sim) {
                    float4 ws4 = *(const float4*)(stp + ST_WS + n * 144 + t * 32 + h2 * 16);
                    bpp[nf][0] = fmaf(am0, ws4.x, wb4.x);
                    bpp[nf][1] = fmaf(am1, ws4.y, wb4.y);
                    bpp[nf][2] = fmaf(am2, ws4.z, wb4.z);
                    bpp[nf][3] = fmaf(am3, ws4.w, wb4.w);
                } else {
                    bpp[nf][0] = wb4.x; bpp[nf][1] = wb4.y;
                    bpp[nf][2] = wb4.z; bpp[nf][3] = wb4.w;
                }
            }
#pragma unroll
            for (int jp = 0; jp < 2; jp++) {
                const int k0 = 16 * h2 + 8 * jp;
                uint32_t a_[4][4];
#pragma unroll
                for (int i = 0; i < 4; i++) {
                    const float* ap = Ab + (size_t)(rb + 16 * i + q) * 36 + k0 + t;
                    a_[i][0] = __float_as_uint(ap[0]);
                    a_[i][1] = __float_as_uint(ap[8 * 36]);
                    a_[i][2] = __float_as_uint(ap[4]);
                    a_[i][3] = __float_as_uint(ap[8 * 36 + 4]);
                }
#pragma unroll
                for (int nf = 0; nf < 4; nf++) {
                    uint32_t b0r = __float_as_uint(bpp[nf][2 * jp]);
                    uint32_t b1r = __float_as_uint(bpp[nf][2 * jp + 1]);
#pragma unroll
                    for (int i = 0; i < 4; i++)
                        mma_tf32(acc[i][nf], a_[i][0], a_[i][1], a_[i][2], a_[i][3], b0r, b1r);
                }
            }
        }

        if (has_sim) {                          // interleaved aproj (coalesced LDG)
            const float* wrow = ap_w + (size_t)(c * 32) * HID;
            const float* amr2 = ap_am + c * 32;
#pragma unroll 8
            for (int kk = 0; kk < 32; kk++)
                aproj_acc += __ldg(amr2 + kk) * __ldg(wrow + (size_t)kk * HID);
        }
        __syncthreads();                        // done reading stage(c)

        if (c + 2 < NCHUNK) stage_chunk(c + 2, sbase, idx_s, cx, tid);
        CP_COMMIT();
    }

    // ---- epilogue ----
    aproj_s[tid] = aproj_acc + b1[an];          // tid == abq*128 + an
    __syncthreads();

    float* part = (float*)(smem + OFF_STAGE);   // [256][4] partials
    const float  bo  = __ldg(b_out);
    const float* apq = aproj_s + mi * 128;
#pragma unroll
    for (int i = 0; i < 4; i++) {
        float s0 = 0.f, s1 = 0.f;               // rows rb+16i+q, rb+16i+q+8
#pragma unroll
        for (int nf = 0; nf < 4; nf++) {
            int n0 = nb + nf * 8 + 2 * t, n1 = n0 + 1;
            float w0 = wout_s[n0], w1 = wout_s[n1];
            float ap0 = apq[n0], ap1 = apq[n1];
            float h;
            h = acc[i][nf][0] + ap0; h = fmaxf(h, 0.f) + 0.01f * fminf(h, 0.f); s0 += h * w0;
            h = acc[i][nf][1] + ap1; h = fmaxf(h, 0.f) + 0.01f * fminf(h, 0.f); s0 += h * w1;
            h = acc[i][nf][2] + ap0; h = fmaxf(h, 0.f) + 0.01f * fminf(h, 0.f); s1 += h * w0;
            h = acc[i][nf][3] + ap1; h = fmaxf(h, 0.f) + 0.01f * fminf(h, 0.f); s1 += h * w1;
        }
        s0 += __shfl_xor_sync(0xffffffffu, s0, 1);
        s0 += __shfl_xor_sync(0xffffffffu, s0, 2);
        s1 += __shfl_xor_sync(0xffffffffu, s1, 1);
        s1 += __shfl_xor_sync(0xffffffffu, s1, 2);
        if (t == 0) {
            part[(rb + 16 * i + q) * 4 + nh]     = s0;
            part[(rb + 16 * i + q + 8) * 4 + nh] = s1;
        }
    }
    __syncthreads();

    if (tid < 256) {
        float sc = part[tid * 4] + part[tid * 4 + 1] + part[tid * 4 + 2] + part[tid * 4 + 3];
        int a = tid & 63, bg = b0 + (tid >> 6);
        if (a < n_ants)
            out[(size_t)bg * (n_ants + 1) + 1 + a] =
                rough[(size_t)bg * n_ants + a] + bo + sc;
        if (a == 0) out[(size_t)bg * (n_ants + 1)] = EPSV;
    }
}

// -------------------- launch --------------------
extern "C" void kernel_launch(void* const* d_in, const int* in_sizes, int n_in,
                              void* d_out, int out_size) {
    const float* all_m = (const float*)d_in[0];
    const float* m_b   = (const float*)d_in[1];
    const float* pw    = (const float*)d_in[2];
    const void*  idx   = d_in[3];
    const float* rough = (const float*)d_in[4];
    const float* W1    = (const float*)d_in[5];
    const float* b1    = (const float*)d_in[6];
    const float* Wo    = (const float*)d_in[7];
    const float* bo    = (const float*)d_in[8];
    float* out = (float*)d_out;

    const int batch  = in_sizes[1] / EMB;     // 512
    const int n_ants = in_sizes[3] / batch;   // 50

    cudaFuncSetAttribute(pair_mma_kernel,
                         cudaFuncAttributeMaxDynamicSharedMemorySize, SMEM_TOTAL);

    transpose_w1_kernel<<<dim3(KSEG / 32, HID / 32), 256>>>(W1, (const unsigned*)idx,
                                                            in_sizes[3]);
    pair_mma_kernel<<<batch / 4, 512, SMEM_TOTAL>>>(all_m, m_b, pw, idx, rough,
                                                    W1, b1, Wo, bo, out, n_ants);
}